// round 11
// baseline (speedup 1.0000x reference)
#include <cuda_runtime.h>
#include <cstdint>
#include <cstddef>

#define NN 100000
#define EE 1600000
#define HD 128
#define CAP 64

typedef unsigned long long ull;

// ---- scratch (__device__ globals; allocations forbidden) ----
__device__ float g_h[(size_t)NN * HD];           // layer buffer A
__device__ float g_h2[(size_t)NN * HD];          // layer buffer B
__device__ float g_hw[(size_t)NN * HD];          // rare-path hw operand
__device__ float g_agg[(size_t)NN * HD];         // rare-path agg operand
__device__ int   g_cnt[NN];
__device__ int   g_col[(size_t)NN * CAP];
__device__ int   g_spill_cnt;
__device__ int2  g_spill[EE];
__device__ int   g_item_cnt[2];                  // rare work items per layer
__device__ int2  g_items[NN / 8 + 64];           // {node_base, mskbits}
// k-major transposed weights (built once per launch)
__device__ __align__(16) float g_WinT[128 * 128];
__device__ __align__(16) float g_WdT[2 * 256 * 128];
__device__ __align__(16) float g_WihT[3 * 128 * 128];
__device__ __align__(16) float g_WhhT[3 * 128 * 128];

__device__ __forceinline__ float sigmoidf_(float x) { return 1.0f / (1.0f + expf(-x)); }
__device__ __forceinline__ float softplusf_(float x) {
    return fmaxf(x, 0.0f) + log1pf(expf(-fabsf(x)));
}

// ---- packed f32x2 helpers (FFMA2 only reachable via PTX) ----
__device__ __forceinline__ ull splat2(float x) {
    ull r; asm("mov.b64 %0, {%1, %1};" : "=l"(r) : "f"(x)); return r;
}
__device__ __forceinline__ ull pack2(float lo, float hi) {
    ull r; asm("mov.b64 %0, {%1, %2};" : "=l"(r) : "f"(lo), "f"(hi)); return r;
}
__device__ __forceinline__ void unpack2(float& lo, float& hi, ull v) {
    asm("mov.b64 {%0, %1}, %2;" : "=f"(lo), "=f"(hi) : "l"(v));
}
__device__ __forceinline__ void fma2(ull& d, ull a, ull b) {
    asm("fma.rn.f32x2 %0, %1, %2, %3;" : "=l"(d) : "l"(a), "l"(b), "l"(d));
}

// ---------------------------------------------------------------------------
// Packed 32-k micro-tile, LOAD-BATCHED: per k4 step, ALL 12 loads (8 A rows +
// 4 weight pairs) are issued first into registers, then 64 FFMA2 run against
// resident operands — one scoreboard drain per k4 instead of interleaved
// load-use chains.
// ---------------------------------------------------------------------------
__device__ __forceinline__ void mma8g(ull acc[8][2], const float* __restrict__ WT,
                                      const float* __restrict__ A, int lda, int aofs,
                                      int i0, int j0) {
#pragma unroll
    for (int k4 = 0; k4 < 8; ++k4) {
        float4 av[8];
#pragma unroll
        for (int u = 0; u < 8; ++u)
            av[u] = *reinterpret_cast<const float4*>(
                A + (size_t)(i0 + u) * lda + aofs + k4 * 4);
        ull w[4][2];
#pragma unroll
        for (int t = 0; t < 4; ++t) {
            const ulonglong2 wv = *reinterpret_cast<const ulonglong2*>(
                WT + (k4 * 4 + t) * 128 + j0);
            w[t][0] = wv.x; w[t][1] = wv.y;
        }
#pragma unroll
        for (int u = 0; u < 8; ++u) {
            ull s;
            s = splat2(av[u].x); fma2(acc[u][0], s, w[0][0]); fma2(acc[u][1], s, w[0][1]);
            s = splat2(av[u].y); fma2(acc[u][0], s, w[1][0]); fma2(acc[u][1], s, w[1][1]);
            s = splat2(av[u].z); fma2(acc[u][0], s, w[2][0]); fma2(acc[u][1], s, w[2][1]);
            s = splat2(av[u].w); fma2(acc[u][0], s, w[3][0]); fma2(acc[u][1], s, w[3][1]);
        }
    }
}

// ---------------------------------------------------------------------------
// prep: weight transposes + counters zero, one kernel.
// ---------------------------------------------------------------------------
__global__ __launch_bounds__(256) void prep_kernel(const float* __restrict__ W_in,
                                                   const float* __restrict__ Wd,
                                                   const float* __restrict__ Wih,
                                                   const float* __restrict__ Whh) {
    const int idx = blockIdx.x * 256 + threadIdx.x;
    if (idx < 16384) {
        const int j = idx >> 7, k = idx & 127;
        g_WinT[k * 128 + j] = W_in[idx];
    } else if (idx < 81920) {
        const int e = idx - 16384;
        const int l = e >> 15, rem = e & 32767;
        const int j = rem >> 8, k = rem & 255;
        g_WdT[l * 32768 + k * 128 + j] = Wd[e];
    } else if (idx < 131072) {
        const int e = idx - 81920;
        const int j = e >> 7, k = e & 127;
        const int g = j >> 7, jj = j & 127;
        g_WihT[g * 16384 + k * 128 + jj] = Wih[e];
    } else if (idx < 180224) {
        const int e = idx - 131072;
        const int j = e >> 7, k = e & 127;
        const int g = j >> 7, jj = j & 127;
        g_WhhT[g * 16384 + k * 128 + jj] = Whh[e];
    } else if (idx < 280224) {
        g_cnt[idx - 180224] = 0;
    } else if (idx == 280224) {
        g_spill_cnt = 0;
        g_item_cnt[0] = 0;
        g_item_cnt[1] = 0;
    }
}

// ---------------------------------------------------------------------------
// h0 = relu(x @ W_in^T + b_in)  -> g_h   (NO forced min-blocks: spills cost
// more than occupancy buys — measured in round 10)
// ---------------------------------------------------------------------------
__global__ __launch_bounds__(128, 4) void in_gemm_kernel(const float* __restrict__ x,
                                                         const float* __restrict__ b) {
    const int node0 = blockIdx.x * 32;
    const int lane = threadIdx.x & 31;
    const int i0 = (threadIdx.x >> 5) * 8, j0 = lane * 4;
    const float* A = x + (size_t)node0 * HD;

    ull acc[8][2];
    {
        const float4 b4 = *reinterpret_cast<const float4*>(b + j0);
        const ull b0 = pack2(b4.x, b4.y), b1 = pack2(b4.z, b4.w);
#pragma unroll
        for (int u = 0; u < 8; ++u) { acc[u][0] = b0; acc[u][1] = b1; }
    }
#pragma unroll 1
    for (int kt = 0; kt < 4; ++kt)
        mma8g(acc, g_WinT + kt * 4096, A, HD, kt * 32, i0, j0);

#pragma unroll
    for (int u = 0; u < 8; ++u) {
        float a0, a1, a2, a3;
        unpack2(a0, a1, acc[u][0]);
        unpack2(a2, a3, acc[u][1]);
        *reinterpret_cast<float4*>(g_h + (size_t)(node0 + i0 + u) * HD + j0) =
            make_float4(fmaxf(a0, 0.f), fmaxf(a1, 0.f), fmaxf(a2, 0.f), fmaxf(a3, 0.f));
    }
}

// ---------------------------------------------------------------------------
// Edge structure: capacity-slot scatter (exact; overflow -> spill list)
// ---------------------------------------------------------------------------
__global__ __launch_bounds__(256) void scatter_kernel(const int* __restrict__ ei) {
    const int idx = blockIdx.x * 256 + threadIdx.x;  // 2 edges/thread
    const int2 r = reinterpret_cast<const int2*>(ei)[idx];
    const int2 c = reinterpret_cast<const int2*>(ei + EE)[idx];
    int pos = atomicAdd(&g_cnt[r.x], 1);
    if (pos < CAP) g_col[(size_t)r.x * CAP + pos] = c.x;
    else { int s = atomicAdd(&g_spill_cnt, 1); g_spill[s] = make_int2(r.x, c.x); }
    pos = atomicAdd(&g_cnt[r.y], 1);
    if (pos < CAP) g_col[(size_t)r.y * CAP + pos] = c.y;
    else { int s = atomicAdd(&g_spill_cnt, 1); g_spill[s] = make_int2(r.y, c.y); }
}

// ---------------------------------------------------------------------------
// HOT fused node kernel (cold GRU evicted to fix_kernel):
//   per-warp gather-agg -> smem; hw = relu([h,agg]@Wd^T+bd); tau; common path
//   writes hout/out. Rare warps spill operands + enqueue item.
// ---------------------------------------------------------------------------
__global__ __launch_bounds__(128, 5) void node_kernel(
    const float* __restrict__ hin, float* __restrict__ hout,
    int layer, const float* __restrict__ bd,
    const float* __restrict__ Wt, const float* __restrict__ bt,
    const float* __restrict__ Wo, const float* __restrict__ bo,
    float* __restrict__ out, float* __restrict__ tau_out) {
    __shared__ float AGG[32 * 128];   // 16 KB, warp-private strips
    const int node0 = blockIdx.x * 32;
    const int lane = threadIdx.x & 31;
    const int i0 = (threadIdx.x >> 5) * 8, j0 = lane * 4;
    const float* WdTl = g_WdT + layer * 32768;
    const float* Ah = hin + (size_t)node0 * HD;

    // ---- phase 0: gather-aggregate this warp's 8 nodes into AGG ----
#pragma unroll 1
    for (int u = 0; u < 8; ++u) {
        const int node = node0 + i0 + u;
        const float4 hi = *reinterpret_cast<const float4*>(hin + (size_t)node * HD + lane * 4);
        float4 a = make_float4(0.f, 0.f, 0.f, 0.f);
        const int deg = min(g_cnt[node], CAP);
        const int* base = g_col + (size_t)node * CAP;
        int e = 0;
        for (; e + 8 <= deg; e += 8) {
            const int4 ia = *reinterpret_cast<const int4*>(base + e);
            const int4 ib = *reinterpret_cast<const int4*>(base + e + 4);
            const float4 v0 = *reinterpret_cast<const float4*>(hin + (size_t)ia.x * HD + lane * 4);
            const float4 v1 = *reinterpret_cast<const float4*>(hin + (size_t)ia.y * HD + lane * 4);
            const float4 v2 = *reinterpret_cast<const float4*>(hin + (size_t)ia.z * HD + lane * 4);
            const float4 v3 = *reinterpret_cast<const float4*>(hin + (size_t)ia.w * HD + lane * 4);
            const float4 v4 = *reinterpret_cast<const float4*>(hin + (size_t)ib.x * HD + lane * 4);
            const float4 v5 = *reinterpret_cast<const float4*>(hin + (size_t)ib.y * HD + lane * 4);
            const float4 v6 = *reinterpret_cast<const float4*>(hin + (size_t)ib.z * HD + lane * 4);
            const float4 v7 = *reinterpret_cast<const float4*>(hin + (size_t)ib.w * HD + lane * 4);
            a.x += fabsf(hi.x - v0.x) + fabsf(hi.x - v1.x) + fabsf(hi.x - v2.x) + fabsf(hi.x - v3.x)
                 + fabsf(hi.x - v4.x) + fabsf(hi.x - v5.x) + fabsf(hi.x - v6.x) + fabsf(hi.x - v7.x);
            a.y += fabsf(hi.y - v0.y) + fabsf(hi.y - v1.y) + fabsf(hi.y - v2.y) + fabsf(hi.y - v3.y)
                 + fabsf(hi.y - v4.y) + fabsf(hi.y - v5.y) + fabsf(hi.y - v6.y) + fabsf(hi.y - v7.y);
            a.z += fabsf(hi.z - v0.z) + fabsf(hi.z - v1.z) + fabsf(hi.z - v2.z) + fabsf(hi.z - v3.z)
                 + fabsf(hi.z - v4.z) + fabsf(hi.z - v5.z) + fabsf(hi.z - v6.z) + fabsf(hi.z - v7.z);
            a.w += fabsf(hi.w - v0.w) + fabsf(hi.w - v1.w) + fabsf(hi.w - v2.w) + fabsf(hi.w - v3.w)
                 + fabsf(hi.w - v4.w) + fabsf(hi.w - v5.w) + fabsf(hi.w - v6.w) + fabsf(hi.w - v7.w);
        }
        for (; e < deg; ++e) {
            const int c0 = base[e];
            const float4 v = *reinterpret_cast<const float4*>(hin + (size_t)c0 * HD + lane * 4);
            a.x += fabsf(hi.x - v.x);
            a.y += fabsf(hi.y - v.y);
            a.z += fabsf(hi.z - v.z);
            a.w += fabsf(hi.w - v.w);
        }
        *reinterpret_cast<float4*>(AGG + (i0 + u) * 128 + j0) = a;
    }
    // exact spill fix-up (empty unless some node degree > CAP)
    {
        const int sc = g_spill_cnt;
        for (int s = 0; s < sc; ++s) {
            const int2 sp = g_spill[s];
            const int rel = sp.x - (node0 + i0);
            if (rel >= 0 && rel < 8) {
                const float4 aa = *reinterpret_cast<const float4*>(hin + (size_t)sp.x * HD + lane * 4);
                const float4 bb = *reinterpret_cast<const float4*>(hin + (size_t)sp.y * HD + lane * 4);
                float4* p = reinterpret_cast<float4*>(AGG + (i0 + rel) * 128 + j0);
                float4 v = *p;
                v.x += fabsf(aa.x - bb.x); v.y += fabsf(aa.y - bb.y);
                v.z += fabsf(aa.z - bb.z); v.w += fabsf(aa.w - bb.w);
                *p = v;
            }
        }
    }
    __syncwarp();

    // ---- phase 1: hw = relu([h,agg] @ Wd^T + bd) ----
    ull acc[8][2];
    {
        const float4 b4 = *reinterpret_cast<const float4*>(bd + j0);
        const ull b0 = pack2(b4.x, b4.y), b1 = pack2(b4.z, b4.w);
#pragma unroll
        for (int u = 0; u < 8; ++u) { acc[u][0] = b0; acc[u][1] = b1; }
    }
#pragma unroll 1
    for (int kt = 0; kt < 4; ++kt)
        mma8g(acc, WdTl + kt * 4096, Ah, HD, kt * 32, i0, j0);
#pragma unroll 1
    for (int kt = 0; kt < 4; ++kt)
        mma8g(acc, WdTl + 16384 + kt * 4096, AGG, 128, kt * 32, i0, j0);

    float hw[8][4];
#pragma unroll
    for (int u = 0; u < 8; ++u) {
        float a0, a1, a2, a3;
        unpack2(a0, a1, acc[u][0]);
        unpack2(a2, a3, acc[u][1]);
        hw[u][0] = fmaxf(a0, 0.f); hw[u][1] = fmaxf(a1, 0.f);
        hw[u][2] = fmaxf(a2, 0.f); hw[u][3] = fmaxf(a3, 0.f);
    }

    // ---- phase 2: tau (uniform across warp) ----
    const float4 wt4 = *reinterpret_cast<const float4*>(Wt + j0);
    const float bt0 = bt[0];
    int mskbits = 0;
#pragma unroll
    for (int u = 0; u < 8; ++u) {
        float p = hw[u][0] * wt4.x + hw[u][1] * wt4.y +
                  hw[u][2] * wt4.z + hw[u][3] * wt4.w;
#pragma unroll
        for (int o = 16; o > 0; o >>= 1) p += __shfl_xor_sync(0xffffffffu, p, o);
        p = __shfl_sync(0xffffffffu, p, 0);
        const float tv = softplusf_(p + bt0);
        if (tau_out && lane == 0) tau_out[node0 + i0 + u] = tv;
        if (tv < 0.005f) mskbits |= 1 << u;
    }

    if (__any_sync(0xffffffffu, mskbits != 0)) {
        // RARE: spill operands, enqueue work item, write nothing else.
#pragma unroll
        for (int u = 0; u < 8; ++u) {
            *reinterpret_cast<float4*>(g_agg + (size_t)(node0 + i0 + u) * HD + j0) =
                *reinterpret_cast<const float4*>(AGG + (i0 + u) * 128 + j0);
            *reinterpret_cast<float4*>(g_hw + (size_t)(node0 + i0 + u) * HD + j0) =
                make_float4(hw[u][0], hw[u][1], hw[u][2], hw[u][3]);
        }
        if (lane == 0) {
            const int s = atomicAdd(&g_item_cnt[layer], 1);
            g_items[s] = make_int2(node0 + i0, mskbits);
        }
        return;
    }

    // ---- common path output ----
    if (out) {
        const float4 wo0 = *reinterpret_cast<const float4*>(Wo + j0);
        const float4 wo1 = *reinterpret_cast<const float4*>(Wo + 128 + j0);
        const float bo0 = bo[0], bo1 = bo[1];
#pragma unroll
        for (int u = 0; u < 8; ++u) {
            float p0 = hw[u][0] * wo0.x + hw[u][1] * wo0.y + hw[u][2] * wo0.z + hw[u][3] * wo0.w;
            float p1 = hw[u][0] * wo1.x + hw[u][1] * wo1.y + hw[u][2] * wo1.z + hw[u][3] * wo1.w;
#pragma unroll
            for (int o = 16; o > 0; o >>= 1) {
                p0 += __shfl_xor_sync(0xffffffffu, p0, o);
                p1 += __shfl_xor_sync(0xffffffffu, p1, o);
            }
            if (lane == 0)
                *reinterpret_cast<float2*>(out + (size_t)(node0 + i0 + u) * 2) =
                    make_float2(p0 + bo0, p1 + bo1);
        }
    } else {
#pragma unroll
        for (int u = 0; u < 8; ++u)
            *reinterpret_cast<float4*>(hout + (size_t)(node0 + i0 + u) * HD + j0) =
                make_float4(hw[u][0], hw[u][1], hw[u][2], hw[u][3]);
    }
}

// ---------------------------------------------------------------------------
// COLD fix-up kernel: exact masked GRU for enqueued warps. Normally 0 items.
// ---------------------------------------------------------------------------
__global__ __launch_bounds__(128) void fix_kernel(
    int layer, float* __restrict__ hout,
    const float* __restrict__ bih, const float* __restrict__ bhh,
    const float* __restrict__ Wo, const float* __restrict__ bo,
    float* __restrict__ out) {
    const int gwid = blockIdx.x * 4 + (threadIdx.x >> 5);
    const int lane = threadIdx.x & 31;
    const int j0 = lane * 4;
    const int n = g_item_cnt[layer];
    for (int it = gwid; it < n; it += 128) {
        const int2 item = g_items[it];
        const int nb = item.x;
        const int mskbits = item.y;
        const float* Aa  = g_agg + (size_t)nb * HD;
        const float* Ahw = g_hw + (size_t)nb * HD;

        float hw[8][4];
#pragma unroll
        for (int u = 0; u < 8; ++u) {
            const float4 v = *reinterpret_cast<const float4*>(Ahw + (size_t)u * HD + j0);
            hw[u][0] = v.x; hw[u][1] = v.y; hw[u][2] = v.z; hw[u][3] = v.w;
        }
        // r gate
        float r_[8][4];
        {
            ull ga[8][2];
            const float4 bi = *reinterpret_cast<const float4*>(bih + j0);
            const float4 bh = *reinterpret_cast<const float4*>(bhh + j0);
            const ull b0 = pack2(bi.x + bh.x, bi.y + bh.y);
            const ull b1 = pack2(bi.z + bh.z, bi.w + bh.w);
#pragma unroll
            for (int u = 0; u < 8; ++u) { ga[u][0] = b0; ga[u][1] = b1; }
#pragma unroll 1
            for (int kt = 0; kt < 4; ++kt)
                mma8g(ga, g_WihT + kt * 4096, Aa, HD, kt * 32, 0, j0);
#pragma unroll 1
            for (int kt = 0; kt < 4; ++kt)
                mma8g(ga, g_WhhT + kt * 4096, Ahw, HD, kt * 32, 0, j0);
#pragma unroll
            for (int u = 0; u < 8; ++u) {
                float a0, a1, a2, a3;
                unpack2(a0, a1, ga[u][0]); unpack2(a2, a3, ga[u][1]);
                r_[u][0] = sigmoidf_(a0); r_[u][1] = sigmoidf_(a1);
                r_[u][2] = sigmoidf_(a2); r_[u][3] = sigmoidf_(a3);
            }
        }
        // rh = r * (bhh_n + hw@Whhn^T)
        float rh[8][4];
        {
            ull hn[8][2];
            const float4 bh = *reinterpret_cast<const float4*>(bhh + 256 + j0);
            const ull b0 = pack2(bh.x, bh.y), b1 = pack2(bh.z, bh.w);
#pragma unroll
            for (int u = 0; u < 8; ++u) { hn[u][0] = b0; hn[u][1] = b1; }
#pragma unroll 1
            for (int kt = 0; kt < 4; ++kt)
                mma8g(hn, g_WhhT + 32768 + kt * 4096, Ahw, HD, kt * 32, 0, j0);
#pragma unroll
            for (int u = 0; u < 8; ++u) {
                float a0, a1, a2, a3;
                unpack2(a0, a1, hn[u][0]); unpack2(a2, a3, hn[u][1]);
                rh[u][0] = r_[u][0] * a0; rh[u][1] = r_[u][1] * a1;
                rh[u][2] = r_[u][2] * a2; rh[u][3] = r_[u][3] * a3;
            }
        }
        // n = tanh(bih_n + agg@Wihn^T + rh)
        float n_[8][4];
        {
            ull in_[8][2];
            const float4 bi = *reinterpret_cast<const float4*>(bih + 256 + j0);
            const ull b0 = pack2(bi.x, bi.y), b1 = pack2(bi.z, bi.w);
#pragma unroll
            for (int u = 0; u < 8; ++u) { in_[u][0] = b0; in_[u][1] = b1; }
#pragma unroll 1
            for (int kt = 0; kt < 4; ++kt)
                mma8g(in_, g_WihT + 32768 + kt * 4096, Aa, HD, kt * 32, 0, j0);
#pragma unroll
            for (int u = 0; u < 8; ++u) {
                float a0, a1, a2, a3;
                unpack2(a0, a1, in_[u][0]); unpack2(a2, a3, in_[u][1]);
                n_[u][0] = tanhf(a0 + rh[u][0]); n_[u][1] = tanhf(a1 + rh[u][1]);
                n_[u][2] = tanhf(a2 + rh[u][2]); n_[u][3] = tanhf(a3 + rh[u][3]);
            }
        }
        // z gate + combine + output
        {
            ull gz[8][2];
            const float4 bi = *reinterpret_cast<const float4*>(bih + 128 + j0);
            const float4 bh = *reinterpret_cast<const float4*>(bhh + 128 + j0);
            const ull b0 = pack2(bi.x + bh.x, bi.y + bh.y);
            const ull b1 = pack2(bi.z + bh.z, bi.w + bh.w);
#pragma unroll
            for (int u = 0; u < 8; ++u) { gz[u][0] = b0; gz[u][1] = b1; }
#pragma unroll 1
            for (int kt = 0; kt < 4; ++kt)
                mma8g(gz, g_WihT + 16384 + kt * 4096, Aa, HD, kt * 32, 0, j0);
#pragma unroll 1
            for (int kt = 0; kt < 4; ++kt)
                mma8g(gz, g_WhhT + 16384 + kt * 4096, Ahw, HD, kt * 32, 0, j0);

            const float4 wo0 = out ? *reinterpret_cast<const float4*>(Wo + j0) : make_float4(0,0,0,0);
            const float4 wo1 = out ? *reinterpret_cast<const float4*>(Wo + 128 + j0) : make_float4(0,0,0,0);
            const float bo0 = out ? bo[0] : 0.f, bo1 = out ? bo[1] : 0.f;
#pragma unroll
            for (int u = 0; u < 8; ++u) {
                float a0, a1, a2, a3;
                unpack2(a0, a1, gz[u][0]); unpack2(a2, a3, gz[u][1]);
                const float zv[4] = {sigmoidf_(a0), sigmoidf_(a1), sigmoidf_(a2), sigmoidf_(a3)};
                const bool msk = (mskbits >> u) & 1;
                float ov[4];
#pragma unroll
                for (int v = 0; v < 4; ++v) {
                    const float hn = (1.0f - zv[v]) * n_[u][v] + zv[v] * hw[u][v];
                    ov[v] = msk ? hn : hw[u][v];
                }
                if (out) {
                    float p0 = ov[0] * wo0.x + ov[1] * wo0.y + ov[2] * wo0.z + ov[3] * wo0.w;
                    float p1 = ov[0] * wo1.x + ov[1] * wo1.y + ov[2] * wo1.z + ov[3] * wo1.w;
#pragma unroll
                    for (int o = 16; o > 0; o >>= 1) {
                        p0 += __shfl_xor_sync(0xffffffffu, p0, o);
                        p1 += __shfl_xor_sync(0xffffffffu, p1, o);
                    }
                    if (lane == 0)
                        *reinterpret_cast<float2*>(out + (size_t)(nb + u) * 2) =
                            make_float2(p0 + bo0, p1 + bo1);
                } else {
                    *reinterpret_cast<float4*>(hout + (size_t)(nb + u) * HD + j0) =
                        make_float4(ov[0], ov[1], ov[2], ov[3]);
                }
            }
        }
    }
}

// ---------------------------------------------------------------------------
extern "C" void kernel_launch(void* const* d_in, const int* in_sizes, int n_in,
                              void* d_out, int out_size) {
    const float* x    = (const float*)d_in[0];
    const int*   ei   = (const int*)d_in[1];   // int32 (JAX x64-disabled)
    const float* W_in = (const float*)d_in[2];
    const float* b_in = (const float*)d_in[3];
    const float* Wd   = (const float*)d_in[4];
    const float* bd   = (const float*)d_in[5];
    const float* Wt   = (const float*)d_in[6];
    const float* bt   = (const float*)d_in[7];
    const float* Wih  = (const float*)d_in[8];
    const float* Whh  = (const float*)d_in[9];
    const float* bih  = (const float*)d_in[10];
    const float* bhh  = (const float*)d_in[11];
    const float* Wo   = (const float*)d_in[12];
    const float* bo   = (const float*)d_in[13];

    float* out = (float*)d_out;
    float* tau_out = (out_size >= NN * 3) ? out + (size_t)NN * 2 : nullptr;

    float *hA, *hB;
    cudaGetSymbolAddress((void**)&hA, g_h);
    cudaGetSymbolAddress((void**)&hB, g_h2);

    prep_kernel<<<(280225 + 255) / 256, 256>>>(W_in, Wd, Wih, Whh);
    scatter_kernel<<<EE / 512, 256>>>(ei);
    in_gemm_kernel<<<NN / 32, 128>>>(x, b_in);   // -> g_h

    // layer 0: hA -> hB ; layer 1: hB -> out
    node_kernel<<<NN / 32, 128>>>(hA, hB, 0, bd, Wt, bt, Wo, bo, nullptr, nullptr);
    fix_kernel<<<32, 128>>>(0, hB, bih, bhh, Wo, bo, nullptr);
    node_kernel<<<NN / 32, 128>>>(hB, nullptr, 1, bd + HD, Wt, bt, Wo, bo, out, tau_out);
    fix_kernel<<<32, 128>>>(1, nullptr, bih, bhh, Wo, bo, out);
}

// round 12
// speedup vs baseline: 1.0040x; 1.0040x over previous
#include <cuda_runtime.h>
#include <cstdint>
#include <cstddef>

#define NN 100000
#define EE 1600000
#define HD 128
#define CAP 64

typedef unsigned long long ull;

// ---- scratch (__device__ globals; allocations forbidden) ----
__device__ float g_h[(size_t)NN * HD];           // layer buffer A
__device__ float g_h2[(size_t)NN * HD];          // layer buffer B
__device__ float g_hw[(size_t)NN * HD];          // rare-path hw operand
__device__ float g_agg[(size_t)NN * HD];         // rare-path agg operand
__device__ int   g_cnt[NN];
__device__ int   g_col[(size_t)NN * CAP];
__device__ int   g_spill_cnt;
__device__ int2  g_spill[EE];
__device__ int   g_item_cnt[2];                  // rare work items per layer
__device__ int2  g_items[NN / 8 + 64];           // {node_base, mskbits}
// k-major transposed weights (built once per launch)
__device__ __align__(16) float g_WinT[128 * 128];
__device__ __align__(16) float g_WdT[2 * 256 * 128];
__device__ __align__(16) float g_WihT[3 * 128 * 128];
__device__ __align__(16) float g_WhhT[3 * 128 * 128];

__device__ __forceinline__ float sigmoidf_(float x) { return 1.0f / (1.0f + expf(-x)); }
__device__ __forceinline__ float softplusf_(float x) {
    return fmaxf(x, 0.0f) + log1pf(expf(-fabsf(x)));
}

// ---- packed f32x2 helpers (FFMA2 only reachable via PTX) ----
__device__ __forceinline__ ull splat2(float x) {
    ull r; asm("mov.b64 %0, {%1, %1};" : "=l"(r) : "f"(x)); return r;
}
__device__ __forceinline__ ull pack2(float lo, float hi) {
    ull r; asm("mov.b64 %0, {%1, %2};" : "=l"(r) : "f"(lo), "f"(hi)); return r;
}
__device__ __forceinline__ void unpack2(float& lo, float& hi, ull v) {
    asm("mov.b64 {%0, %1}, %2;" : "=f"(lo), "=f"(hi) : "l"(v));
}
__device__ __forceinline__ void fma2(ull& d, ull a, ull b) {
    asm("fma.rn.f32x2 %0, %1, %2, %3;" : "=l"(d) : "l"(a), "l"(b), "l"(d));
}

// ---------------------------------------------------------------------------
// Batched 32-k micro-tile (used by in_gemm / agg-half / fix paths)
// ---------------------------------------------------------------------------
__device__ __forceinline__ void mma8g(ull acc[8][2], const float* __restrict__ WT,
                                      const float* __restrict__ A, int lda, int aofs,
                                      int i0, int j0) {
#pragma unroll
    for (int k4 = 0; k4 < 8; ++k4) {
        ull w[4][2];
#pragma unroll
        for (int t = 0; t < 4; ++t) {
            const ulonglong2 wv = *reinterpret_cast<const ulonglong2*>(
                WT + (k4 * 4 + t) * 128 + j0);
            w[t][0] = wv.x; w[t][1] = wv.y;
        }
#pragma unroll
        for (int half = 0; half < 2; ++half) {
            float4 av[4];
#pragma unroll
            for (int uu = 0; uu < 4; ++uu)
                av[uu] = *reinterpret_cast<const float4*>(
                    A + (size_t)(i0 + half * 4 + uu) * lda + aofs + k4 * 4);
#pragma unroll
            for (int uu = 0; uu < 4; ++uu) {
                const int u = half * 4 + uu;
                ull s;
                s = splat2(av[uu].x); fma2(acc[u][0], s, w[0][0]); fma2(acc[u][1], s, w[0][1]);
                s = splat2(av[uu].y); fma2(acc[u][0], s, w[1][0]); fma2(acc[u][1], s, w[1][1]);
                s = splat2(av[uu].z); fma2(acc[u][0], s, w[2][0]); fma2(acc[u][1], s, w[2][1]);
                s = splat2(av[uu].w); fma2(acc[u][0], s, w[3][0]); fma2(acc[u][1], s, w[3][1]);
            }
        }
    }
}

// One k4-step (4 k-values): weights at Wp (k-major strip, row t at Wp+t*128),
// A columns [aoff, aoff+4).
__device__ __forceinline__ void mma_step(ull acc[8][2], const float* __restrict__ Wp,
                                         const float* __restrict__ A, int aoff,
                                         int i0, int j0) {
    ull w[4][2];
#pragma unroll
    for (int t = 0; t < 4; ++t) {
        const ulonglong2 wv = *reinterpret_cast<const ulonglong2*>(Wp + t * 128 + j0);
        w[t][0] = wv.x; w[t][1] = wv.y;
    }
#pragma unroll
    for (int half = 0; half < 2; ++half) {
        float4 av[4];
#pragma unroll
        for (int uu = 0; uu < 4; ++uu)
            av[uu] = *reinterpret_cast<const float4*>(
                A + (size_t)(i0 + half * 4 + uu) * HD + aoff);
#pragma unroll
        for (int uu = 0; uu < 4; ++uu) {
            const int u = half * 4 + uu;
            ull s;
            s = splat2(av[uu].x); fma2(acc[u][0], s, w[0][0]); fma2(acc[u][1], s, w[0][1]);
            s = splat2(av[uu].y); fma2(acc[u][0], s, w[1][0]); fma2(acc[u][1], s, w[1][1]);
            s = splat2(av[uu].z); fma2(acc[u][0], s, w[2][0]); fma2(acc[u][1], s, w[2][1]);
            s = splat2(av[uu].w); fma2(acc[u][0], s, w[3][0]); fma2(acc[u][1], s, w[3][1]);
        }
    }
}

// ---------------------------------------------------------------------------
// prep: weight transposes + counters zero, one kernel.
// ---------------------------------------------------------------------------
__global__ __launch_bounds__(256) void prep_kernel(const float* __restrict__ W_in,
                                                   const float* __restrict__ Wd,
                                                   const float* __restrict__ Wih,
                                                   const float* __restrict__ Whh) {
    const int idx = blockIdx.x * 256 + threadIdx.x;
    if (idx < 16384) {
        const int j = idx >> 7, k = idx & 127;
        g_WinT[k * 128 + j] = W_in[idx];
    } else if (idx < 81920) {
        const int e = idx - 16384;
        const int l = e >> 15, rem = e & 32767;
        const int j = rem >> 8, k = rem & 255;
        g_WdT[l * 32768 + k * 128 + j] = Wd[e];
    } else if (idx < 131072) {
        const int e = idx - 81920;
        const int j = e >> 7, k = e & 127;
        const int g = j >> 7, jj = j & 127;
        g_WihT[g * 16384 + k * 128 + jj] = Wih[e];
    } else if (idx < 180224) {
        const int e = idx - 131072;
        const int j = e >> 7, k = e & 127;
        const int g = j >> 7, jj = j & 127;
        g_WhhT[g * 16384 + k * 128 + jj] = Whh[e];
    } else if (idx < 280224) {
        g_cnt[idx - 180224] = 0;
    } else if (idx == 280224) {
        g_spill_cnt = 0;
        g_item_cnt[0] = 0;
        g_item_cnt[1] = 0;
    }
}

// ---------------------------------------------------------------------------
// h0 = relu(x @ W_in^T + b_in)  -> g_h
// ---------------------------------------------------------------------------
__global__ __launch_bounds__(128, 4) void in_gemm_kernel(const float* __restrict__ x,
                                                         const float* __restrict__ b) {
    const int node0 = blockIdx.x * 32;
    const int lane = threadIdx.x & 31;
    const int i0 = (threadIdx.x >> 5) * 8, j0 = lane * 4;
    const float* A = x + (size_t)node0 * HD;

    ull acc[8][2];
    {
        const float4 b4 = *reinterpret_cast<const float4*>(b + j0);
        const ull b0 = pack2(b4.x, b4.y), b1 = pack2(b4.z, b4.w);
#pragma unroll
        for (int u = 0; u < 8; ++u) { acc[u][0] = b0; acc[u][1] = b1; }
    }
#pragma unroll 1
    for (int kt = 0; kt < 4; ++kt)
        mma8g(acc, g_WinT + kt * 4096, A, HD, kt * 32, i0, j0);

#pragma unroll
    for (int u = 0; u < 8; ++u) {
        float a0, a1, a2, a3;
        unpack2(a0, a1, acc[u][0]);
        unpack2(a2, a3, acc[u][1]);
        *reinterpret_cast<float4*>(g_h + (size_t)(node0 + i0 + u) * HD + j0) =
            make_float4(fmaxf(a0, 0.f), fmaxf(a1, 0.f), fmaxf(a2, 0.f), fmaxf(a3, 0.f));
    }
}

// ---------------------------------------------------------------------------
// Edge structure: capacity-slot scatter (exact; overflow -> spill list)
// ---------------------------------------------------------------------------
__global__ __launch_bounds__(256) void scatter_kernel(const int* __restrict__ ei) {
    const int idx = blockIdx.x * 256 + threadIdx.x;  // 2 edges/thread
    const int2 r = reinterpret_cast<const int2*>(ei)[idx];
    const int2 c = reinterpret_cast<const int2*>(ei + EE)[idx];
    int pos = atomicAdd(&g_cnt[r.x], 1);
    if (pos < CAP) g_col[(size_t)r.x * CAP + pos] = c.x;
    else { int s = atomicAdd(&g_spill_cnt, 1); g_spill[s] = make_int2(r.x, c.x); }
    pos = atomicAdd(&g_cnt[r.y], 1);
    if (pos < CAP) g_col[(size_t)r.y * CAP + pos] = c.y;
    else { int s = atomicAdd(&g_spill_cnt, 1); g_spill[s] = make_int2(r.y, c.y); }
}

// ---------------------------------------------------------------------------
// HOT fused node kernel with gather/GEMM interleave:
//   for each of the warp's 8 nodes: issue an 8-neighbor gather batch (self-
//   index padded, divergence-free), run 1-2 h-half GEMM k4-steps while the
//   loads drain, consume the batch. 3 batches/node (deg<=24; exact serial
//   tail + spill list beyond). AGG written once per node. Then agg-half GEMM
//   from smem, tau, per-warp rare enqueue, output.
// ---------------------------------------------------------------------------
__global__ __launch_bounds__(128, 4) void node_kernel(
    const float* __restrict__ hin, float* __restrict__ hout,
    int layer, const float* __restrict__ bd,
    const float* __restrict__ Wt, const float* __restrict__ bt,
    const float* __restrict__ Wo, const float* __restrict__ bo,
    float* __restrict__ out, float* __restrict__ tau_out) {
    __shared__ float AGG[32 * 128];   // 16 KB, warp-private strips
    const int node0 = blockIdx.x * 32;
    const int lane = threadIdx.x & 31;
    const int i0 = (threadIdx.x >> 5) * 8, j0 = lane * 4;
    const float* WdTl = g_WdT + layer * 32768;
    const float* Ah = hin + (size_t)node0 * HD;

    // ---- interleaved phase: gather + h-half GEMM (32 k4-steps total) ----
    ull acc[8][2];
    {
        const float4 b4 = *reinterpret_cast<const float4*>(bd + j0);
        const ull b0 = pack2(b4.x, b4.y), b1 = pack2(b4.z, b4.w);
#pragma unroll
        for (int u = 0; u < 8; ++u) { acc[u][0] = b0; acc[u][1] = b1; }
    }

#pragma unroll 1
    for (int u = 0; u < 8; ++u) {
        const int node = node0 + i0 + u;
        const int deg = min(g_cnt[node], CAP);
        const int* base = g_col + (size_t)node * CAP;
        const float4 hi = *reinterpret_cast<const float4*>(hin + (size_t)node * HD + j0);
        float4 g = make_float4(0.f, 0.f, 0.f, 0.f);
        const int s0 = u * 4;   // this node's 4 k4-steps: s0..s0+3
#pragma unroll
        for (int q = 0; q < 3; ++q) {
            const int e0 = q * 8;
            // issue gather batch (self-index pad: OOB slots -> own row -> diff 0)
            const int4 ia = *reinterpret_cast<const int4*>(base + e0);
            const int4 ib = *reinterpret_cast<const int4*>(base + e0 + 4);
            const int c0 = (e0 + 0 < deg) ? ia.x : node;
            const int c1 = (e0 + 1 < deg) ? ia.y : node;
            const int c2 = (e0 + 2 < deg) ? ia.z : node;
            const int c3 = (e0 + 3 < deg) ? ia.w : node;
            const int c4 = (e0 + 4 < deg) ? ib.x : node;
            const int c5 = (e0 + 5 < deg) ? ib.y : node;
            const int c6 = (e0 + 6 < deg) ? ib.z : node;
            const int c7 = (e0 + 7 < deg) ? ib.w : node;
            const float4 v0 = *reinterpret_cast<const float4*>(hin + (size_t)c0 * HD + j0);
            const float4 v1 = *reinterpret_cast<const float4*>(hin + (size_t)c1 * HD + j0);
            const float4 v2 = *reinterpret_cast<const float4*>(hin + (size_t)c2 * HD + j0);
            const float4 v3 = *reinterpret_cast<const float4*>(hin + (size_t)c3 * HD + j0);
            const float4 v4 = *reinterpret_cast<const float4*>(hin + (size_t)c4 * HD + j0);
            const float4 v5 = *reinterpret_cast<const float4*>(hin + (size_t)c5 * HD + j0);
            const float4 v6 = *reinterpret_cast<const float4*>(hin + (size_t)c6 * HD + j0);
            const float4 v7 = *reinterpret_cast<const float4*>(hin + (size_t)c7 * HD + j0);
            // run GEMM k4-steps while the gather drains (q0: 2 steps; q1/q2: 1)
            if (q == 0) {
                mma_step(acc, WdTl + (s0 + 0) * 512, Ah, (s0 + 0) * 4, i0, j0);
                mma_step(acc, WdTl + (s0 + 1) * 512, Ah, (s0 + 1) * 4, i0, j0);
            } else {
                mma_step(acc, WdTl + (s0 + 1 + q) * 512, Ah, (s0 + 1 + q) * 4, i0, j0);
            }
            // consume
            g.x += fabsf(hi.x - v0.x) + fabsf(hi.x - v1.x) + fabsf(hi.x - v2.x) + fabsf(hi.x - v3.x)
                 + fabsf(hi.x - v4.x) + fabsf(hi.x - v5.x) + fabsf(hi.x - v6.x) + fabsf(hi.x - v7.x);
            g.y += fabsf(hi.y - v0.y) + fabsf(hi.y - v1.y) + fabsf(hi.y - v2.y) + fabsf(hi.y - v3.y)
                 + fabsf(hi.y - v4.y) + fabsf(hi.y - v5.y) + fabsf(hi.y - v6.y) + fabsf(hi.y - v7.y);
            g.z += fabsf(hi.z - v0.z) + fabsf(hi.z - v1.z) + fabsf(hi.z - v2.z) + fabsf(hi.z - v3.z)
                 + fabsf(hi.z - v4.z) + fabsf(hi.z - v5.z) + fabsf(hi.z - v6.z) + fabsf(hi.z - v7.z);
            g.w += fabsf(hi.w - v0.w) + fabsf(hi.w - v1.w) + fabsf(hi.w - v2.w) + fabsf(hi.w - v3.w)
                 + fabsf(hi.w - v4.w) + fabsf(hi.w - v5.w) + fabsf(hi.w - v6.w) + fabsf(hi.w - v7.w);
        }
        // exact tail for deg > 24 (P ~ 2%)
        for (int e = 24; e < deg; ++e) {
            const int c = base[e];
            const float4 v = *reinterpret_cast<const float4*>(hin + (size_t)c * HD + j0);
            g.x += fabsf(hi.x - v.x);
            g.y += fabsf(hi.y - v.y);
            g.z += fabsf(hi.z - v.z);
            g.w += fabsf(hi.w - v.w);
        }
        *reinterpret_cast<float4*>(AGG + (i0 + u) * 128 + j0) = g;
    }
    // exact spill fix-up (empty unless some node degree > CAP)
    {
        const int sc = g_spill_cnt;
        for (int s = 0; s < sc; ++s) {
            const int2 sp = g_spill[s];
            const int rel = sp.x - (node0 + i0);
            if (rel >= 0 && rel < 8) {
                const float4 aa = *reinterpret_cast<const float4*>(hin + (size_t)sp.x * HD + j0);
                const float4 bb = *reinterpret_cast<const float4*>(hin + (size_t)sp.y * HD + j0);
                float4* p = reinterpret_cast<float4*>(AGG + (i0 + rel) * 128 + j0);
                float4 v = *p;
                v.x += fabsf(aa.x - bb.x); v.y += fabsf(aa.y - bb.y);
                v.z += fabsf(aa.z - bb.z); v.w += fabsf(aa.w - bb.w);
                *p = v;
            }
        }
    }
    __syncwarp();

    // ---- agg-half GEMM from smem ----
#pragma unroll 1
    for (int kt = 0; kt < 4; ++kt)
        mma8g(acc, WdTl + 16384 + kt * 4096, AGG, 128, kt * 32, i0, j0);

    float hw[8][4];
#pragma unroll
    for (int u = 0; u < 8; ++u) {
        float a0, a1, a2, a3;
        unpack2(a0, a1, acc[u][0]);
        unpack2(a2, a3, acc[u][1]);
        hw[u][0] = fmaxf(a0, 0.f); hw[u][1] = fmaxf(a1, 0.f);
        hw[u][2] = fmaxf(a2, 0.f); hw[u][3] = fmaxf(a3, 0.f);
    }

    // ---- tau (uniform across warp) ----
    const float4 wt4 = *reinterpret_cast<const float4*>(Wt + j0);
    const float bt0 = bt[0];
    int mskbits = 0;
#pragma unroll
    for (int u = 0; u < 8; ++u) {
        float p = hw[u][0] * wt4.x + hw[u][1] * wt4.y +
                  hw[u][2] * wt4.z + hw[u][3] * wt4.w;
#pragma unroll
        for (int o = 16; o > 0; o >>= 1) p += __shfl_xor_sync(0xffffffffu, p, o);
        p = __shfl_sync(0xffffffffu, p, 0);
        const float tv = softplusf_(p + bt0);
        if (tau_out && lane == 0) tau_out[node0 + i0 + u] = tv;
        if (tv < 0.005f) mskbits |= 1 << u;
    }

    if (__any_sync(0xffffffffu, mskbits != 0)) {
        // RARE: spill operands, enqueue work item, write nothing else.
#pragma unroll
        for (int u = 0; u < 8; ++u) {
            *reinterpret_cast<float4*>(g_agg + (size_t)(node0 + i0 + u) * HD + j0) =
                *reinterpret_cast<const float4*>(AGG + (i0 + u) * 128 + j0);
            *reinterpret_cast<float4*>(g_hw + (size_t)(node0 + i0 + u) * HD + j0) =
                make_float4(hw[u][0], hw[u][1], hw[u][2], hw[u][3]);
        }
        if (lane == 0) {
            const int s = atomicAdd(&g_item_cnt[layer], 1);
            g_items[s] = make_int2(node0 + i0, mskbits);
        }
        return;
    }

    // ---- common path output ----
    if (out) {
        const float4 wo0 = *reinterpret_cast<const float4*>(Wo + j0);
        const float4 wo1 = *reinterpret_cast<const float4*>(Wo + 128 + j0);
        const float bo0 = bo[0], bo1 = bo[1];
#pragma unroll
        for (int u = 0; u < 8; ++u) {
            float p0 = hw[u][0] * wo0.x + hw[u][1] * wo0.y + hw[u][2] * wo0.z + hw[u][3] * wo0.w;
            float p1 = hw[u][0] * wo1.x + hw[u][1] * wo1.y + hw[u][2] * wo1.z + hw[u][3] * wo1.w;
#pragma unroll
            for (int o = 16; o > 0; o >>= 1) {
                p0 += __shfl_xor_sync(0xffffffffu, p0, o);
                p1 += __shfl_xor_sync(0xffffffffu, p1, o);
            }
            if (lane == 0)
                *reinterpret_cast<float2*>(out + (size_t)(node0 + i0 + u) * 2) =
                    make_float2(p0 + bo0, p1 + bo1);
        }
    } else {
#pragma unroll
        for (int u = 0; u < 8; ++u)
            *reinterpret_cast<float4*>(hout + (size_t)(node0 + i0 + u) * HD + j0) =
                make_float4(hw[u][0], hw[u][1], hw[u][2], hw[u][3]);
    }
}

// ---------------------------------------------------------------------------
// COLD fix-up kernel: exact masked GRU for enqueued warps. Normally 0 items.
// ---------------------------------------------------------------------------
__global__ __launch_bounds__(128) void fix_kernel(
    int layer, float* __restrict__ hout,
    const float* __restrict__ bih, const float* __restrict__ bhh,
    const float* __restrict__ Wo, const float* __restrict__ bo,
    float* __restrict__ out) {
    const int gwid = blockIdx.x * 4 + (threadIdx.x >> 5);
    const int lane = threadIdx.x & 31;
    const int j0 = lane * 4;
    const int n = g_item_cnt[layer];
    for (int it = gwid; it < n; it += 128) {
        const int2 item = g_items[it];
        const int nb = item.x;
        const int mskbits = item.y;
        const float* Aa  = g_agg + (size_t)nb * HD;
        const float* Ahw = g_hw + (size_t)nb * HD;

        float hw[8][4];
#pragma unroll
        for (int u = 0; u < 8; ++u) {
            const float4 v = *reinterpret_cast<const float4*>(Ahw + (size_t)u * HD + j0);
            hw[u][0] = v.x; hw[u][1] = v.y; hw[u][2] = v.z; hw[u][3] = v.w;
        }
        // r gate
        float r_[8][4];
        {
            ull ga[8][2];
            const float4 bi = *reinterpret_cast<const float4*>(bih + j0);
            const float4 bh = *reinterpret_cast<const float4*>(bhh + j0);
            const ull b0 = pack2(bi.x + bh.x, bi.y + bh.y);
            const ull b1 = pack2(bi.z + bh.z, bi.w + bh.w);
#pragma unroll
            for (int u = 0; u < 8; ++u) { ga[u][0] = b0; ga[u][1] = b1; }
#pragma unroll 1
            for (int kt = 0; kt < 4; ++kt)
                mma8g(ga, g_WihT + kt * 4096, Aa, HD, kt * 32, 0, j0);
#pragma unroll 1
            for (int kt = 0; kt < 4; ++kt)
                mma8g(ga, g_WhhT + kt * 4096, Ahw, HD, kt * 32, 0, j0);
#pragma unroll
            for (int u = 0; u < 8; ++u) {
                float a0, a1, a2, a3;
                unpack2(a0, a1, ga[u][0]); unpack2(a2, a3, ga[u][1]);
                r_[u][0] = sigmoidf_(a0); r_[u][1] = sigmoidf_(a1);
                r_[u][2] = sigmoidf_(a2); r_[u][3] = sigmoidf_(a3);
            }
        }
        // rh = r * (bhh_n + hw@Whhn^T)
        float rh[8][4];
        {
            ull hn[8][2];
            const float4 bh = *reinterpret_cast<const float4*>(bhh + 256 + j0);
            const ull b0 = pack2(bh.x, bh.y), b1 = pack2(bh.z, bh.w);
#pragma unroll
            for (int u = 0; u < 8; ++u) { hn[u][0] = b0; hn[u][1] = b1; }
#pragma unroll 1
            for (int kt = 0; kt < 4; ++kt)
                mma8g(hn, g_WhhT + 32768 + kt * 4096, Ahw, HD, kt * 32, 0, j0);
#pragma unroll
            for (int u = 0; u < 8; ++u) {
                float a0, a1, a2, a3;
                unpack2(a0, a1, hn[u][0]); unpack2(a2, a3, hn[u][1]);
                rh[u][0] = r_[u][0] * a0; rh[u][1] = r_[u][1] * a1;
                rh[u][2] = r_[u][2] * a2; rh[u][3] = r_[u][3] * a3;
            }
        }
        // n = tanh(bih_n + agg@Wihn^T + rh)
        float n_[8][4];
        {
            ull in_[8][2];
            const float4 bi = *reinterpret_cast<const float4*>(bih + 256 + j0);
            const ull b0 = pack2(bi.x, bi.y), b1 = pack2(bi.z, bi.w);
#pragma unroll
            for (int u = 0; u < 8; ++u) { in_[u][0] = b0; in_[u][1] = b1; }
#pragma unroll 1
            for (int kt = 0; kt < 4; ++kt)
                mma8g(in_, g_WihT + 32768 + kt * 4096, Aa, HD, kt * 32, 0, j0);
#pragma unroll
            for (int u = 0; u < 8; ++u) {
                float a0, a1, a2, a3;
                unpack2(a0, a1, in_[u][0]); unpack2(a2, a3, in_[u][1]);
                n_[u][0] = tanhf(a0 + rh[u][0]); n_[u][1] = tanhf(a1 + rh[u][1]);
                n_[u][2] = tanhf(a2 + rh[u][2]); n_[u][3] = tanhf(a3 + rh[u][3]);
            }
        }
        // z gate + combine + output
        {
            ull gz[8][2];
            const float4 bi = *reinterpret_cast<const float4*>(bih + 128 + j0);
            const float4 bh = *reinterpret_cast<const float4*>(bhh + 128 + j0);
            const ull b0 = pack2(bi.x + bh.x, bi.y + bh.y);
            const ull b1 = pack2(bi.z + bh.z, bi.w + bh.w);
#pragma unroll
            for (int u = 0; u < 8; ++u) { gz[u][0] = b0; gz[u][1] = b1; }
#pragma unroll 1
            for (int kt = 0; kt < 4; ++kt)
                mma8g(gz, g_WihT + 16384 + kt * 4096, Aa, HD, kt * 32, 0, j0);
#pragma unroll 1
            for (int kt = 0; kt < 4; ++kt)
                mma8g(gz, g_WhhT + 16384 + kt * 4096, Ahw, HD, kt * 32, 0, j0);

            const float4 wo0 = out ? *reinterpret_cast<const float4*>(Wo + j0) : make_float4(0,0,0,0);
            const float4 wo1 = out ? *reinterpret_cast<const float4*>(Wo + 128 + j0) : make_float4(0,0,0,0);
            const float bo0 = out ? bo[0] : 0.f, bo1 = out ? bo[1] : 0.f;
#pragma unroll
            for (int u = 0; u < 8; ++u) {
                float a0, a1, a2, a3;
                unpack2(a0, a1, gz[u][0]); unpack2(a2, a3, gz[u][1]);
                const float zv[4] = {sigmoidf_(a0), sigmoidf_(a1), sigmoidf_(a2), sigmoidf_(a3)};
                const bool msk = (mskbits >> u) & 1;
                float ov[4];
#pragma unroll
                for (int v = 0; v < 4; ++v) {
                    const float hn = (1.0f - zv[v]) * n_[u][v] + zv[v] * hw[u][v];
                    ov[v] = msk ? hn : hw[u][v];
                }
                if (out) {
                    float p0 = ov[0] * wo0.x + ov[1] * wo0.y + ov[2] * wo0.z + ov[3] * wo0.w;
                    float p1 = ov[0] * wo1.x + ov[1] * wo1.y + ov[2] * wo1.z + ov[3] * wo1.w;
#pragma unroll
                    for (int o = 16; o > 0; o >>= 1) {
                        p0 += __shfl_xor_sync(0xffffffffu, p0, o);
                        p1 += __shfl_xor_sync(0xffffffffu, p1, o);
                    }
                    if (lane == 0)
                        *reinterpret_cast<float2*>(out + (size_t)(nb + u) * 2) =
                            make_float2(p0 + bo0, p1 + bo1);
                } else {
                    *reinterpret_cast<float4*>(hout + (size_t)(nb + u) * HD + j0) =
                        make_float4(ov[0], ov[1], ov[2], ov[3]);
                }
            }
        }
    }
}

// ---------------------------------------------------------------------------
extern "C" void kernel_launch(void* const* d_in, const int* in_sizes, int n_in,
                              void* d_out, int out_size) {
    const float* x    = (const float*)d_in[0];
    const int*   ei   = (const int*)d_in[1];   // int32 (JAX x64-disabled)
    const float* W_in = (const float*)d_in[2];
    const float* b_in = (const float*)d_in[3];
    const float* Wd   = (const float*)d_in[4];
    const float* bd   = (const float*)d_in[5];
    const float* Wt   = (const float*)d_in[6];
    const float* bt   = (const float*)d_in[7];
    const float* Wih  = (const float*)d_in[8];
    const float* Whh  = (const float*)d_in[9];
    const float* bih  = (const float*)d_in[10];
    const float* bhh  = (const float*)d_in[11];
    const float* Wo   = (const float*)d_in[12];
    const float* bo   = (const float*)d_in[13];

    float* out = (float*)d_out;
    float* tau_out = (out_size >= NN * 3) ? out + (size_t)NN * 2 : nullptr;

    float *hA, *hB;
    cudaGetSymbolAddress((void**)&hA, g_h);
    cudaGetSymbolAddress((void**)&hB, g_h2);

    prep_kernel<<<(280225 + 255) / 256, 256>>>(W_in, Wd, Wih, Whh);
    scatter_kernel<<<EE / 512, 256>>>(ei);
    in_gemm_kernel<<<NN / 32, 128>>>(x, b_in);   // -> g_h

    // layer 0: hA -> hB ; layer 1: hB -> out
    node_kernel<<<NN / 32, 128>>>(hA, hB, 0, bd, Wt, bt, Wo, bo, nullptr, nullptr);
    fix_kernel<<<32, 128>>>(0, hB, bih, bhh, Wo, bo, nullptr);
    node_kernel<<<NN / 32, 128>>>(hB, nullptr, 1, bd + HD, Wt, bt, Wo, bo, out, tau_out);
    fix_kernel<<<32, 128>>>(1, nullptr, bih, bhh, Wo, bo, out);
}

// round 13
// speedup vs baseline: 1.1957x; 1.1909x over previous
#include <cuda_runtime.h>
#include <cstdint>
#include <cstddef>

#define NN 100000
#define EE 1600000
#define HD 128
#define CAP 64

typedef unsigned long long ull;

// ---- scratch (__device__ globals; allocations forbidden) ----
__device__ float g_h[(size_t)NN * HD];           // layer buffer A
__device__ float g_h2[(size_t)NN * HD];          // layer buffer B
__device__ float g_hw[(size_t)NN * HD];          // masked-node hw operand
__device__ float g_agg[(size_t)NN * HD];         // masked-node agg operand
__device__ int   g_cnt[NN];
__device__ int   g_col[(size_t)NN * CAP];
__device__ int   g_spill_cnt;
__device__ int2  g_spill[EE];
__device__ int   g_item_cnt[2];                  // masked nodes per layer
__device__ int   g_items[2][NN];                 // masked node ids
// k-major transposed weights (built once per launch)
__device__ __align__(16) float g_WinT[128 * 128];
__device__ __align__(16) float g_WdT[2 * 256 * 128];
__device__ __align__(16) float g_WihT[3 * 128 * 128];
__device__ __align__(16) float g_WhhT[3 * 128 * 128];

__device__ __forceinline__ float sigmoidf_(float x) { return 1.0f / (1.0f + expf(-x)); }
__device__ __forceinline__ float softplusf_(float x) {
    return fmaxf(x, 0.0f) + log1pf(expf(-fabsf(x)));
}

// ---- packed f32x2 helpers (FFMA2 only reachable via PTX) ----
__device__ __forceinline__ ull splat2(float x) {
    ull r; asm("mov.b64 %0, {%1, %1};" : "=l"(r) : "f"(x)); return r;
}
__device__ __forceinline__ ull pack2(float lo, float hi) {
    ull r; asm("mov.b64 %0, {%1, %2};" : "=l"(r) : "f"(lo), "f"(hi)); return r;
}
__device__ __forceinline__ void unpack2(float& lo, float& hi, ull v) {
    asm("mov.b64 {%0, %1}, %2;" : "=f"(lo), "=f"(hi) : "l"(v));
}
__device__ __forceinline__ void fma2(ull& d, ull a, ull b) {
    asm("fma.rn.f32x2 %0, %1, %2, %3;" : "=l"(d) : "l"(a), "l"(b), "l"(d));
}

// ---------------------------------------------------------------------------
// Batched 32-k micro-tile over contiguous rows
// ---------------------------------------------------------------------------
__device__ __forceinline__ void mma8g(ull acc[8][2], const float* __restrict__ WT,
                                      const float* __restrict__ A, int lda, int aofs,
                                      int i0, int j0) {
#pragma unroll
    for (int k4 = 0; k4 < 8; ++k4) {
        ull w[4][2];
#pragma unroll
        for (int t = 0; t < 4; ++t) {
            const ulonglong2 wv = *reinterpret_cast<const ulonglong2*>(
                WT + (k4 * 4 + t) * 128 + j0);
            w[t][0] = wv.x; w[t][1] = wv.y;
        }
#pragma unroll
        for (int half = 0; half < 2; ++half) {
            float4 av[4];
#pragma unroll
            for (int uu = 0; uu < 4; ++uu)
                av[uu] = *reinterpret_cast<const float4*>(
                    A + (size_t)(i0 + half * 4 + uu) * lda + aofs + k4 * 4);
#pragma unroll
            for (int uu = 0; uu < 4; ++uu) {
                const int u = half * 4 + uu;
                ull s;
                s = splat2(av[uu].x); fma2(acc[u][0], s, w[0][0]); fma2(acc[u][1], s, w[0][1]);
                s = splat2(av[uu].y); fma2(acc[u][0], s, w[1][0]); fma2(acc[u][1], s, w[1][1]);
                s = splat2(av[uu].z); fma2(acc[u][0], s, w[2][0]); fma2(acc[u][1], s, w[2][1]);
                s = splat2(av[uu].w); fma2(acc[u][0], s, w[3][0]); fma2(acc[u][1], s, w[3][1]);
            }
        }
    }
}

// Same, but rows indirected through node ids (masked-node fix path).
__device__ __forceinline__ void mma8i(ull acc[8][2], const float* __restrict__ WT,
                                      const float* __restrict__ base, const int* ids,
                                      int aofs, int j0) {
#pragma unroll
    for (int k4 = 0; k4 < 8; ++k4) {
        ull w[4][2];
#pragma unroll
        for (int t = 0; t < 4; ++t) {
            const ulonglong2 wv = *reinterpret_cast<const ulonglong2*>(
                WT + (k4 * 4 + t) * 128 + j0);
            w[t][0] = wv.x; w[t][1] = wv.y;
        }
#pragma unroll
        for (int half = 0; half < 2; ++half) {
            float4 av[4];
#pragma unroll
            for (int uu = 0; uu < 4; ++uu)
                av[uu] = *reinterpret_cast<const float4*>(
                    base + (size_t)ids[half * 4 + uu] * HD + aofs + k4 * 4);
#pragma unroll
            for (int uu = 0; uu < 4; ++uu) {
                const int u = half * 4 + uu;
                ull s;
                s = splat2(av[uu].x); fma2(acc[u][0], s, w[0][0]); fma2(acc[u][1], s, w[0][1]);
                s = splat2(av[uu].y); fma2(acc[u][0], s, w[1][0]); fma2(acc[u][1], s, w[1][1]);
                s = splat2(av[uu].z); fma2(acc[u][0], s, w[2][0]); fma2(acc[u][1], s, w[2][1]);
                s = splat2(av[uu].w); fma2(acc[u][0], s, w[3][0]); fma2(acc[u][1], s, w[3][1]);
            }
        }
    }
}

// One k4-step for the gather/GEMM interleave
__device__ __forceinline__ void mma_step(ull acc[8][2], const float* __restrict__ Wp,
                                         const float* __restrict__ A, int aoff,
                                         int i0, int j0) {
    ull w[4][2];
#pragma unroll
    for (int t = 0; t < 4; ++t) {
        const ulonglong2 wv = *reinterpret_cast<const ulonglong2*>(Wp + t * 128 + j0);
        w[t][0] = wv.x; w[t][1] = wv.y;
    }
#pragma unroll
    for (int half = 0; half < 2; ++half) {
        float4 av[4];
#pragma unroll
        for (int uu = 0; uu < 4; ++uu)
            av[uu] = *reinterpret_cast<const float4*>(
                A + (size_t)(i0 + half * 4 + uu) * HD + aoff);
#pragma unroll
        for (int uu = 0; uu < 4; ++uu) {
            const int u = half * 4 + uu;
            ull s;
            s = splat2(av[uu].x); fma2(acc[u][0], s, w[0][0]); fma2(acc[u][1], s, w[0][1]);
            s = splat2(av[uu].y); fma2(acc[u][0], s, w[1][0]); fma2(acc[u][1], s, w[1][1]);
            s = splat2(av[uu].z); fma2(acc[u][0], s, w[2][0]); fma2(acc[u][1], s, w[2][1]);
            s = splat2(av[uu].w); fma2(acc[u][0], s, w[3][0]); fma2(acc[u][1], s, w[3][1]);
        }
    }
}

// ---------------------------------------------------------------------------
// prep: weight transposes + counters zero, one kernel.
// ---------------------------------------------------------------------------
__global__ __launch_bounds__(256) void prep_kernel(const float* __restrict__ W_in,
                                                   const float* __restrict__ Wd,
                                                   const float* __restrict__ Wih,
                                                   const float* __restrict__ Whh) {
    const int idx = blockIdx.x * 256 + threadIdx.x;
    if (idx < 16384) {
        const int j = idx >> 7, k = idx & 127;
        g_WinT[k * 128 + j] = W_in[idx];
    } else if (idx < 81920) {
        const int e = idx - 16384;
        const int l = e >> 15, rem = e & 32767;
        const int j = rem >> 8, k = rem & 255;
        g_WdT[l * 32768 + k * 128 + j] = Wd[e];
    } else if (idx < 131072) {
        const int e = idx - 81920;
        const int j = e >> 7, k = e & 127;
        const int g = j >> 7, jj = j & 127;
        g_WihT[g * 16384 + k * 128 + jj] = Wih[e];
    } else if (idx < 180224) {
        const int e = idx - 131072;
        const int j = e >> 7, k = e & 127;
        const int g = j >> 7, jj = j & 127;
        g_WhhT[g * 16384 + k * 128 + jj] = Whh[e];
    } else if (idx < 280224) {
        g_cnt[idx - 180224] = 0;
    } else if (idx == 280224) {
        g_spill_cnt = 0;
        g_item_cnt[0] = 0;
        g_item_cnt[1] = 0;
    }
}

// ---------------------------------------------------------------------------
// h0 = relu(x @ W_in^T + b_in)  -> g_h
// ---------------------------------------------------------------------------
__global__ __launch_bounds__(128, 4) void in_gemm_kernel(const float* __restrict__ x,
                                                         const float* __restrict__ b) {
    const int node0 = blockIdx.x * 32;
    const int lane = threadIdx.x & 31;
    const int i0 = (threadIdx.x >> 5) * 8, j0 = lane * 4;
    const float* A = x + (size_t)node0 * HD;

    ull acc[8][2];
    {
        const float4 b4 = *reinterpret_cast<const float4*>(b + j0);
        const ull b0 = pack2(b4.x, b4.y), b1 = pack2(b4.z, b4.w);
#pragma unroll
        for (int u = 0; u < 8; ++u) { acc[u][0] = b0; acc[u][1] = b1; }
    }
#pragma unroll 1
    for (int kt = 0; kt < 4; ++kt)
        mma8g(acc, g_WinT + kt * 4096, A, HD, kt * 32, i0, j0);

#pragma unroll
    for (int u = 0; u < 8; ++u) {
        float a0, a1, a2, a3;
        unpack2(a0, a1, acc[u][0]);
        unpack2(a2, a3, acc[u][1]);
        *reinterpret_cast<float4*>(g_h + (size_t)(node0 + i0 + u) * HD + j0) =
            make_float4(fmaxf(a0, 0.f), fmaxf(a1, 0.f), fmaxf(a2, 0.f), fmaxf(a3, 0.f));
    }
}

// ---------------------------------------------------------------------------
// Edge structure: capacity-slot scatter (exact; overflow -> spill list)
// ---------------------------------------------------------------------------
__global__ __launch_bounds__(256) void scatter_kernel(const int* __restrict__ ei) {
    const int idx = blockIdx.x * 256 + threadIdx.x;  // 2 edges/thread
    const int2 r = reinterpret_cast<const int2*>(ei)[idx];
    const int2 c = reinterpret_cast<const int2*>(ei + EE)[idx];
    int pos = atomicAdd(&g_cnt[r.x], 1);
    if (pos < CAP) g_col[(size_t)r.x * CAP + pos] = c.x;
    else { int s = atomicAdd(&g_spill_cnt, 1); g_spill[s] = make_int2(r.x, c.x); }
    pos = atomicAdd(&g_cnt[r.y], 1);
    if (pos < CAP) g_col[(size_t)r.y * CAP + pos] = c.y;
    else { int s = atomicAdd(&g_spill_cnt, 1); g_spill[s] = make_int2(r.y, c.y); }
}

// ---------------------------------------------------------------------------
// HOT fused node kernel (gather/GEMM interleave; masked NODES enqueued
// individually — unmasked nodes in mixed warps still take the fast output).
// ---------------------------------------------------------------------------
__global__ __launch_bounds__(128, 4) void node_kernel(
    const float* __restrict__ hin, float* __restrict__ hout,
    int layer, const float* __restrict__ bd,
    const float* __restrict__ Wt, const float* __restrict__ bt,
    const float* __restrict__ Wo, const float* __restrict__ bo,
    float* __restrict__ out, float* __restrict__ tau_out) {
    __shared__ float AGG[32 * 128];   // 16 KB, warp-private strips
    const int node0 = blockIdx.x * 32;
    const int lane = threadIdx.x & 31;
    const int i0 = (threadIdx.x >> 5) * 8, j0 = lane * 4;
    const float* WdTl = g_WdT + layer * 32768;
    const float* Ah = hin + (size_t)node0 * HD;

    // ---- interleaved phase: gather + h-half GEMM ----
    ull acc[8][2];
    {
        const float4 b4 = *reinterpret_cast<const float4*>(bd + j0);
        const ull b0 = pack2(b4.x, b4.y), b1 = pack2(b4.z, b4.w);
#pragma unroll
        for (int u = 0; u < 8; ++u) { acc[u][0] = b0; acc[u][1] = b1; }
    }

#pragma unroll 1
    for (int u = 0; u < 8; ++u) {
        const int node = node0 + i0 + u;
        const int deg = min(g_cnt[node], CAP);
        const int* base = g_col + (size_t)node * CAP;
        const float4 hi = *reinterpret_cast<const float4*>(hin + (size_t)node * HD + j0);
        float4 g = make_float4(0.f, 0.f, 0.f, 0.f);
        const int s0 = u * 4;
#pragma unroll
        for (int q = 0; q < 3; ++q) {
            const int e0 = q * 8;
            const int4 ia = *reinterpret_cast<const int4*>(base + e0);
            const int4 ib = *reinterpret_cast<const int4*>(base + e0 + 4);
            const int c0 = (e0 + 0 < deg) ? ia.x : node;
            const int c1 = (e0 + 1 < deg) ? ia.y : node;
            const int c2 = (e0 + 2 < deg) ? ia.z : node;
            const int c3 = (e0 + 3 < deg) ? ia.w : node;
            const int c4 = (e0 + 4 < deg) ? ib.x : node;
            const int c5 = (e0 + 5 < deg) ? ib.y : node;
            const int c6 = (e0 + 6 < deg) ? ib.z : node;
            const int c7 = (e0 + 7 < deg) ? ib.w : node;
            const float4 v0 = *reinterpret_cast<const float4*>(hin + (size_t)c0 * HD + j0);
            const float4 v1 = *reinterpret_cast<const float4*>(hin + (size_t)c1 * HD + j0);
            const float4 v2 = *reinterpret_cast<const float4*>(hin + (size_t)c2 * HD + j0);
            const float4 v3 = *reinterpret_cast<const float4*>(hin + (size_t)c3 * HD + j0);
            const float4 v4 = *reinterpret_cast<const float4*>(hin + (size_t)c4 * HD + j0);
            const float4 v5 = *reinterpret_cast<const float4*>(hin + (size_t)c5 * HD + j0);
            const float4 v6 = *reinterpret_cast<const float4*>(hin + (size_t)c6 * HD + j0);
            const float4 v7 = *reinterpret_cast<const float4*>(hin + (size_t)c7 * HD + j0);
            if (q == 0) {
                mma_step(acc, WdTl + (s0 + 0) * 512, Ah, (s0 + 0) * 4, i0, j0);
                mma_step(acc, WdTl + (s0 + 1) * 512, Ah, (s0 + 1) * 4, i0, j0);
            } else {
                mma_step(acc, WdTl + (s0 + 1 + q) * 512, Ah, (s0 + 1 + q) * 4, i0, j0);
            }
            g.x += fabsf(hi.x - v0.x) + fabsf(hi.x - v1.x) + fabsf(hi.x - v2.x) + fabsf(hi.x - v3.x)
                 + fabsf(hi.x - v4.x) + fabsf(hi.x - v5.x) + fabsf(hi.x - v6.x) + fabsf(hi.x - v7.x);
            g.y += fabsf(hi.y - v0.y) + fabsf(hi.y - v1.y) + fabsf(hi.y - v2.y) + fabsf(hi.y - v3.y)
                 + fabsf(hi.y - v4.y) + fabsf(hi.y - v5.y) + fabsf(hi.y - v6.y) + fabsf(hi.y - v7.y);
            g.z += fabsf(hi.z - v0.z) + fabsf(hi.z - v1.z) + fabsf(hi.z - v2.z) + fabsf(hi.z - v3.z)
                 + fabsf(hi.z - v4.z) + fabsf(hi.z - v5.z) + fabsf(hi.z - v6.z) + fabsf(hi.z - v7.z);
            g.w += fabsf(hi.w - v0.w) + fabsf(hi.w - v1.w) + fabsf(hi.w - v2.w) + fabsf(hi.w - v3.w)
                 + fabsf(hi.w - v4.w) + fabsf(hi.w - v5.w) + fabsf(hi.w - v6.w) + fabsf(hi.w - v7.w);
        }
        for (int e = 24; e < deg; ++e) {
            const int c = base[e];
            const float4 v = *reinterpret_cast<const float4*>(hin + (size_t)c * HD + j0);
            g.x += fabsf(hi.x - v.x);
            g.y += fabsf(hi.y - v.y);
            g.z += fabsf(hi.z - v.z);
            g.w += fabsf(hi.w - v.w);
        }
        *reinterpret_cast<float4*>(AGG + (i0 + u) * 128 + j0) = g;
    }
    // exact spill fix-up (empty unless some node degree > CAP)
    {
        const int sc = g_spill_cnt;
        for (int s = 0; s < sc; ++s) {
            const int2 sp = g_spill[s];
            const int rel = sp.x - (node0 + i0);
            if (rel >= 0 && rel < 8) {
                const float4 aa = *reinterpret_cast<const float4*>(hin + (size_t)sp.x * HD + j0);
                const float4 bb = *reinterpret_cast<const float4*>(hin + (size_t)sp.y * HD + j0);
                float4* p = reinterpret_cast<float4*>(AGG + (i0 + rel) * 128 + j0);
                float4 v = *p;
                v.x += fabsf(aa.x - bb.x); v.y += fabsf(aa.y - bb.y);
                v.z += fabsf(aa.z - bb.z); v.w += fabsf(aa.w - bb.w);
                *p = v;
            }
        }
    }
    __syncwarp();

    // ---- agg-half GEMM from smem ----
#pragma unroll 1
    for (int kt = 0; kt < 4; ++kt)
        mma8g(acc, WdTl + 16384 + kt * 4096, AGG, 128, kt * 32, i0, j0);

    float hw[8][4];
#pragma unroll
    for (int u = 0; u < 8; ++u) {
        float a0, a1, a2, a3;
        unpack2(a0, a1, acc[u][0]);
        unpack2(a2, a3, acc[u][1]);
        hw[u][0] = fmaxf(a0, 0.f); hw[u][1] = fmaxf(a1, 0.f);
        hw[u][2] = fmaxf(a2, 0.f); hw[u][3] = fmaxf(a3, 0.f);
    }

    // ---- tau (uniform across warp) ----
    const float4 wt4 = *reinterpret_cast<const float4*>(Wt + j0);
    const float bt0 = bt[0];
    int mskbits = 0;
#pragma unroll
    for (int u = 0; u < 8; ++u) {
        float p = hw[u][0] * wt4.x + hw[u][1] * wt4.y +
                  hw[u][2] * wt4.z + hw[u][3] * wt4.w;
#pragma unroll
        for (int o = 16; o > 0; o >>= 1) p += __shfl_xor_sync(0xffffffffu, p, o);
        p = __shfl_sync(0xffffffffu, p, 0);
        const float tv = softplusf_(p + bt0);
        if (tau_out && lane == 0) tau_out[node0 + i0 + u] = tv;
        if (tv < 0.005f) mskbits |= 1 << u;
    }

    const float4 wo0 = out ? *reinterpret_cast<const float4*>(Wo + j0) : make_float4(0,0,0,0);
    const float4 wo1 = out ? *reinterpret_cast<const float4*>(Wo + 128 + j0) : make_float4(0,0,0,0);
    const float bo0 = out ? bo[0] : 0.f, bo1 = out ? bo[1] : 0.f;

#pragma unroll
    for (int u = 0; u < 8; ++u) {
        const int node = node0 + i0 + u;
        if ((mskbits >> u) & 1) {
            // masked node: spill operands for fix_kernel; enqueue id
            *reinterpret_cast<float4*>(g_agg + (size_t)node * HD + j0) =
                *reinterpret_cast<const float4*>(AGG + (i0 + u) * 128 + j0);
            *reinterpret_cast<float4*>(g_hw + (size_t)node * HD + j0) =
                make_float4(hw[u][0], hw[u][1], hw[u][2], hw[u][3]);
            if (lane == 0) {
                const int s = atomicAdd(&g_item_cnt[layer], 1);
                g_items[layer][s] = node;
            }
        } else if (out) {
            float p0 = hw[u][0] * wo0.x + hw[u][1] * wo0.y + hw[u][2] * wo0.z + hw[u][3] * wo0.w;
            float p1 = hw[u][0] * wo1.x + hw[u][1] * wo1.y + hw[u][2] * wo1.z + hw[u][3] * wo1.w;
#pragma unroll
            for (int o = 16; o > 0; o >>= 1) {
                p0 += __shfl_xor_sync(0xffffffffu, p0, o);
                p1 += __shfl_xor_sync(0xffffffffu, p1, o);
            }
            if (lane == 0)
                *reinterpret_cast<float2*>(out + (size_t)node * 2) =
                    make_float2(p0 + bo0, p1 + bo1);
        } else {
            *reinterpret_cast<float4*>(hout + (size_t)node * HD + j0) =
                make_float4(hw[u][0], hw[u][1], hw[u][2], hw[u][3]);
        }
    }
}

// ---------------------------------------------------------------------------
// COLD fix-up: exact GRU for the enqueued MASKED nodes, 8 packed per warp
// via indirect row indexing (weights amortized 8x). All enqueued nodes take
// the GRU output (only masked nodes are enqueued).
// ---------------------------------------------------------------------------
__global__ __launch_bounds__(128) void fix_kernel(
    int layer, float* __restrict__ hout,
    const float* __restrict__ bih, const float* __restrict__ bhh,
    const float* __restrict__ Wo, const float* __restrict__ bo,
    float* __restrict__ out) {
    const int n = g_item_cnt[layer];
    if (n == 0) return;
    const int lane = threadIdx.x & 31;
    const int j0 = lane * 4;
    const int gw = blockIdx.x * 4 + (threadIdx.x >> 5);
    const int nwarps = gridDim.x * 4;
    const int ngroups = (n + 7) >> 3;

    for (int g = gw; g < ngroups; g += nwarps) {
        int ids[8];
#pragma unroll
        for (int u = 0; u < 8; ++u) {
            int idx = g * 8 + u;
            if (idx >= n) idx = n - 1;   // pad with last id (duplicate identical writes)
            ids[u] = g_items[layer][idx];
        }
        float hw[8][4];
#pragma unroll
        for (int u = 0; u < 8; ++u) {
            const float4 v = *reinterpret_cast<const float4*>(g_hw + (size_t)ids[u] * HD + j0);
            hw[u][0] = v.x; hw[u][1] = v.y; hw[u][2] = v.z; hw[u][3] = v.w;
        }
        // r gate
        float r_[8][4];
        {
            ull ga[8][2];
            const float4 bi = *reinterpret_cast<const float4*>(bih + j0);
            const float4 bh = *reinterpret_cast<const float4*>(bhh + j0);
            const ull b0 = pack2(bi.x + bh.x, bi.y + bh.y);
            const ull b1 = pack2(bi.z + bh.z, bi.w + bh.w);
#pragma unroll
            for (int u = 0; u < 8; ++u) { ga[u][0] = b0; ga[u][1] = b1; }
#pragma unroll 1
            for (int kt = 0; kt < 4; ++kt)
                mma8i(ga, g_WihT + kt * 4096, g_agg, ids, kt * 32, j0);
#pragma unroll 1
            for (int kt = 0; kt < 4; ++kt)
                mma8i(ga, g_WhhT + kt * 4096, g_hw, ids, kt * 32, j0);
#pragma unroll
            for (int u = 0; u < 8; ++u) {
                float a0, a1, a2, a3;
                unpack2(a0, a1, ga[u][0]); unpack2(a2, a3, ga[u][1]);
                r_[u][0] = sigmoidf_(a0); r_[u][1] = sigmoidf_(a1);
                r_[u][2] = sigmoidf_(a2); r_[u][3] = sigmoidf_(a3);
            }
        }
        // rh = r * (bhh_n + hw@Whhn^T)
        float rh[8][4];
        {
            ull hn[8][2];
            const float4 bh = *reinterpret_cast<const float4*>(bhh + 256 + j0);
            const ull b0 = pack2(bh.x, bh.y), b1 = pack2(bh.z, bh.w);
#pragma unroll
            for (int u = 0; u < 8; ++u) { hn[u][0] = b0; hn[u][1] = b1; }
#pragma unroll 1
            for (int kt = 0; kt < 4; ++kt)
                mma8i(hn, g_WhhT + 32768 + kt * 4096, g_hw, ids, kt * 32, j0);
#pragma unroll
            for (int u = 0; u < 8; ++u) {
                float a0, a1, a2, a3;
                unpack2(a0, a1, hn[u][0]); unpack2(a2, a3, hn[u][1]);
                rh[u][0] = r_[u][0] * a0; rh[u][1] = r_[u][1] * a1;
                rh[u][2] = r_[u][2] * a2; rh[u][3] = r_[u][3] * a3;
            }
        }
        // n = tanh(bih_n + agg@Wihn^T + rh)
        float n_[8][4];
        {
            ull in_[8][2];
            const float4 bi = *reinterpret_cast<const float4*>(bih + 256 + j0);
            const ull b0 = pack2(bi.x, bi.y), b1 = pack2(bi.z, bi.w);
#pragma unroll
            for (int u = 0; u < 8; ++u) { in_[u][0] = b0; in_[u][1] = b1; }
#pragma unroll 1
            for (int kt = 0; kt < 4; ++kt)
                mma8i(in_, g_WihT + 32768 + kt * 4096, g_agg, ids, kt * 32, j0);
#pragma unroll
            for (int u = 0; u < 8; ++u) {
                float a0, a1, a2, a3;
                unpack2(a0, a1, in_[u][0]); unpack2(a2, a3, in_[u][1]);
                n_[u][0] = tanhf(a0 + rh[u][0]); n_[u][1] = tanhf(a1 + rh[u][1]);
                n_[u][2] = tanhf(a2 + rh[u][2]); n_[u][3] = tanhf(a3 + rh[u][3]);
            }
        }
        // z gate + combine + output (always GRU value: enqueued => masked)
        {
            ull gz[8][2];
            const float4 bi = *reinterpret_cast<const float4*>(bih + 128 + j0);
            const float4 bh = *reinterpret_cast<const float4*>(bhh + 128 + j0);
            const ull b0 = pack2(bi.x + bh.x, bi.y + bh.y);
            const ull b1 = pack2(bi.z + bh.z, bi.w + bh.w);
#pragma unroll
            for (int u = 0; u < 8; ++u) { gz[u][0] = b0; gz[u][1] = b1; }
#pragma unroll 1
            for (int kt = 0; kt < 4; ++kt)
                mma8i(gz, g_WihT + 16384 + kt * 4096, g_agg, ids, kt * 32, j0);
#pragma unroll 1
            for (int kt = 0; kt < 4; ++kt)
                mma8i(gz, g_WhhT + 16384 + kt * 4096, g_hw, ids, kt * 32, j0);

            const float4 wo0 = out ? *reinterpret_cast<const float4*>(Wo + j0) : make_float4(0,0,0,0);
            const float4 wo1 = out ? *reinterpret_cast<const float4*>(Wo + 128 + j0) : make_float4(0,0,0,0);
            const float bo0 = out ? bo[0] : 0.f, bo1 = out ? bo[1] : 0.f;
#pragma unroll
            for (int u = 0; u < 8; ++u) {
                float a0, a1, a2, a3;
                unpack2(a0, a1, gz[u][0]); unpack2(a2, a3, gz[u][1]);
                const float zv[4] = {sigmoidf_(a0), sigmoidf_(a1), sigmoidf_(a2), sigmoidf_(a3)};
                float ov[4];
#pragma unroll
                for (int v = 0; v < 4; ++v)
                    ov[v] = (1.0f - zv[v]) * n_[u][v] + zv[v] * hw[u][v];
                if (out) {
                    float p0 = ov[0] * wo0.x + ov[1] * wo0.y + ov[2] * wo0.z + ov[3] * wo0.w;
                    float p1 = ov[0] * wo1.x + ov[1] * wo1.y + ov[2] * wo1.z + ov[3] * wo1.w;
#pragma unroll
                    for (int o = 16; o > 0; o >>= 1) {
                        p0 += __shfl_xor_sync(0xffffffffu, p0, o);
                        p1 += __shfl_xor_sync(0xffffffffu, p1, o);
                    }
                    if (lane == 0)
                        *reinterpret_cast<float2*>(out + (size_t)ids[u] * 2) =
                            make_float2(p0 + bo0, p1 + bo1);
                } else {
                    *reinterpret_cast<float4*>(hout + (size_t)ids[u] * HD + j0) =
                        make_float4(ov[0], ov[1], ov[2], ov[3]);
                }
            }
        }
    }
}

// ---------------------------------------------------------------------------
extern "C" void kernel_launch(void* const* d_in, const int* in_sizes, int n_in,
                              void* d_out, int out_size) {
    const float* x    = (const float*)d_in[0];
    const int*   ei   = (const int*)d_in[1];   // int32 (JAX x64-disabled)
    const float* W_in = (const float*)d_in[2];
    const float* b_in = (const float*)d_in[3];
    const float* Wd   = (const float*)d_in[4];
    const float* bd   = (const float*)d_in[5];
    const float* Wt   = (const float*)d_in[6];
    const float* bt   = (const float*)d_in[7];
    const float* Wih  = (const float*)d_in[8];
    const float* Whh  = (const float*)d_in[9];
    const float* bih  = (const float*)d_in[10];
    const float* bhh  = (const float*)d_in[11];
    const float* Wo   = (const float*)d_in[12];
    const float* bo   = (const float*)d_in[13];

    float* out = (float*)d_out;
    float* tau_out = (out_size >= NN * 3) ? out + (size_t)NN * 2 : nullptr;

    float *hA, *hB;
    cudaGetSymbolAddress((void**)&hA, g_h);
    cudaGetSymbolAddress((void**)&hB, g_h2);

    prep_kernel<<<(280225 + 255) / 256, 256>>>(W_in, Wd, Wih, Whh);
    scatter_kernel<<<EE / 512, 256>>>(ei);
    in_gemm_kernel<<<NN / 32, 128>>>(x, b_in);   // -> g_h

    // layer 0: hA -> hB ; layer 1: hB -> out
    node_kernel<<<NN / 32, 128>>>(hA, hB, 0, bd, Wt, bt, Wo, bo, nullptr, nullptr);
    fix_kernel<<<128, 128>>>(0, hB, bih, bhh, Wo, bo, nullptr);
    node_kernel<<<NN / 32, 128>>>(hB, nullptr, 1, bd + HD, Wt, bt, Wo, bo, out, tau_out);
    fix_kernel<<<128, 128>>>(1, nullptr, bih, bhh, Wo, bo, out);
}